// round 2
// baseline (speedup 1.0000x reference)
#include <cuda_runtime.h>
#include <math.h>

// ---------------- problem constants ----------------
// B_IN=64, B_OUT=20, B_INV=20, BATCH=16, F_IN=16, F_OUT=32, N_GRID=24
// 2*B_IN = 128 (input beta/alpha), 2*B_INV = 40 (output grid)
// spec size = B_OUT^2 = 400, SO3 packed size = sum (2l+1)^2 = 10660
#define NSPEC 400
#define NSO3  10660
#define NZO   512          // 16*32
#define SCALING 0.008164965809277261f   // 1/sqrt(15000)

// ---------------- device scratch (allocation-free) ----------------
__device__ double g_lf[64];
__device__ double g_quadw[128];
__device__ float  g_ws2[128 * NSPEC];          // [beta_in][lm]
__device__ float2 g_Fk[24 * NSPEC];            // [p][lm]
__device__ float2 g_Yc[32 * NSPEC * 16];       // [o][lm][i]  (= conj(Y)*SCALING)
__device__ float  g_dinv[40 * NSO3];           // [b][j]
__device__ float2 g_X[16 * NSPEC * 16];        // [z][lm][i]
__device__ float2 g_Z[NZO * NSO3];             // [zo][j]

// ---------------- helpers ----------------
__device__ __forceinline__ int off3(int l) { return l * (4 * l * l - 1) / 3; }

__device__ __forceinline__ int l_of_lm(int lm) {
    int l = (int)sqrtf((float)lm);
    while ((l + 1) * (l + 1) <= lm) l++;
    while (l * l > lm) l--;
    return l;
}

__device__ __forceinline__ int l_of_j(int j) {
    int l = (int)cbrtf(0.75f * (float)j + 0.3f);
    if (l > 19) l = 19;
    while (l < 19 && off3(l + 1) <= j) l++;
    while (l > 0 && off3(l) > j) l--;
    return l;
}

// Wigner small-d d^l_{m,n}(beta), double precision, ratio recurrence over s
// (one exp + two pow at loop start, then pure multiplies)
__device__ double wig_d(int l, int m, int n, double beta) {
    double cb = cos(0.5 * beta), sb = sin(0.5 * beta);
    int s0 = max(0, n - m);
    int s1 = min(l + n, l - m);
    if (s0 > s1) return 0.0;
    double pref = 0.5 * (g_lf[l + m] + g_lf[l - m] + g_lf[l + n] + g_lf[l - n]);
    double c0 = pref - (g_lf[l + n - s0] + g_lf[s0] + g_lf[m - n + s0] + g_lf[l - m - s0]);
    double t = exp(c0) * pow(cb, (double)(2 * l + n - m - 2 * s0)) * pow(sb, (double)(m - n + 2 * s0));
    if ((m - n + s0) & 1) t = -t;
    double val = t;
    double tb2 = (sb * sb) / (cb * cb);
    for (int s = s0; s < s1; s++) {
        double r = ((double)(l + n - s) * (double)(l - m - s)) /
                   ((double)(s + 1) * (double)(m - n + s + 1));
        t = -t * r * tb2;
        val += t;
    }
    return val;
}

// ---------------- const generation ----------------
__global__ void k_setup() {
    int t = threadIdx.x;
    if (t == 0) {
        g_lf[0] = 0.0;
        double a = 0.0;
        for (int k = 1; k < 64; k++) { a += log((double)k); g_lf[k] = a; }
    }
    if (t < 128) {
        // SOFT quadrature weights, b = 64
        double th = M_PI * (2 * t + 1) / 256.0;
        double s = 0.0;
        for (int k = 0; k < 64; k++) s += sin((2 * k + 1) * th) / (2 * k + 1);
        g_quadw[t] = (2.0 / 64.0) * sin(th) * s;
    }
}

__global__ void k_ws2() {
    int id = blockIdx.x * blockDim.x + threadIdx.x;
    if (id >= 128 * NSPEC) return;
    int lm = id % NSPEC, b = id / NSPEC;
    int l = l_of_lm(lm);
    int m = lm - l * l - l;
    double beta = M_PI * (2 * b + 1) / 256.0;
    g_ws2[b * NSPEC + lm] = (float)(g_quadw[b] * wig_d(l, m, 0, beta));
}

__global__ void k_fk() {
    int id = blockIdx.x * blockDim.x + threadIdx.x;
    if (id >= 24 * NSPEC) return;
    int lm = id % NSPEC, p = id / NSPEC;
    int l = l_of_lm(lm);
    int m = lm - l * l - l;
    double beta = (M_PI / 24.0) * (double)(p / 8 + 1);
    int ai = p % 8;                       // alpha = ai * pi/4
    double d = wig_d(l, m, 0, beta);
    double sa, ca;
    sincospi(-(double)(m * ai) / 4.0, &sa, &ca);   // e^{-i m alpha}
    g_Fk[p * NSPEC + lm] = make_float2((float)(d * ca), (float)(d * sa));
}

__global__ void k_dinv() {
    int id = blockIdx.x * blockDim.x + threadIdx.x;
    if (id >= 40 * NSO3) return;
    int j = id % NSO3, b = id / NSO3;
    int l = l_of_j(j);
    int rem = j - off3(l);
    int w = 2 * l + 1;
    int mi = rem / w, ni = rem % w;
    double beta = M_PI * (2 * b + 1) / 80.0;
    g_dinv[b * NSO3 + j] = (float)((double)(2 * l + 1) * wig_d(l, mi - l, ni - l, beta));
}

// Yc[o][lm][i] = SCALING * sum_p kernel[i][o][p] * conj(F_k[p][lm])
__global__ void k_Y(const float* __restrict__ ker) {
    int id = blockIdx.x * blockDim.x + threadIdx.x;
    if (id >= 32 * NSPEC * 16) return;
    int i = id % 16;
    int lm = (id / 16) % NSPEC;
    int o = id / (16 * NSPEC);
    float ar = 0.f, ai = 0.f;
    for (int p = 0; p < 24; p++) {
        float kv = ker[(i * 32 + o) * 24 + p];
        float2 f = g_Fk[p * NSPEC + lm];
        ar += kv * f.x;
        ai += kv * f.y;
    }
    g_Yc[id] = make_float2(SCALING * ar, -SCALING * ai);   // conj
}

// ---------------- alpha-DFT + beta quadrature (fused), block per (z,i) ----------------
__global__ void k_xfX(const float* __restrict__ x) {
    extern __shared__ float sm[];
    float*  xs  = sm;                                // 128*128
    float2* dft = (float2*)(sm + 128 * 128);         // [a][mi] 128*39
    float2* xfs = dft + 128 * 39;                    // [b][mi] 128*39
    int zi = blockIdx.x;
    int tid = threadIdx.x;
    const float* xp = x + (size_t)zi * 16384;
    for (int t = tid; t < 16384; t += blockDim.x) xs[t] = xp[t];
    for (int t = tid; t < 128 * 39; t += blockDim.x) {
        int a = t / 39, mi = t % 39;
        float s, c;
        sincospif(-(float)((mi - 19) * a) / 64.0f, &s, &c);  // e^{-2pi i m a / 128}
        dft[a * 39 + mi] = make_float2(c, s);
    }
    __syncthreads();
    for (int t = tid; t < 128 * 39; t += blockDim.x) {
        int b = t / 39, mi = t % 39;
        float ar = 0.f, ai = 0.f;
        const float* row = xs + b * 128;
        #pragma unroll 4
        for (int a = 0; a < 128; a++) {
            float2 w = dft[a * 39 + mi];
            float v = row[a];
            ar += v * w.x;
            ai += v * w.y;
        }
        xfs[b * 39 + mi] = make_float2(ar, ai);
    }
    __syncthreads();
    int z = zi / 16, i = zi % 16;
    for (int lm = tid; lm < NSPEC; lm += blockDim.x) {
        int l = l_of_lm(lm);
        int m = lm - l * l - l;
        int mi = m + 19;
        float ar = 0.f, ai = 0.f;
        for (int b = 0; b < 128; b++) {
            float w = g_ws2[b * NSPEC + lm];
            float2 v = xfs[b * 39 + mi];
            ar += w * v.x;
            ai += w * v.y;
        }
        g_X[(z * NSPEC + lm) * 16 + i] = make_float2(ar, ai);
    }
}

// ---------------- Z[zo][j] = sum_i X[z,i,lm_m] * Yc[o,lm_n,i], block per zo ----------------
__global__ void k_Z() {
    extern __shared__ float2 sm2[];
    float2* Xs = sm2;          // [i][400]
    float2* Ys = sm2 + 6400;   // [i][400]
    int zo = blockIdx.x;
    int z = zo / 32, o = zo % 32;
    int tid = threadIdx.x;
    for (int t = tid; t < 6400; t += blockDim.x) {
        int lm = t / 16, i = t % 16;
        Xs[i * NSPEC + lm] = g_X[z * 6400 + t];
        Ys[i * NSPEC + lm] = g_Yc[o * 6400 + t];
    }
    __syncthreads();
    for (int j = tid; j < NSO3; j += blockDim.x) {
        int l = l_of_j(j);
        int rem = j - off3(l);
        int w = 2 * l + 1;
        int mi = rem / w, ni = rem % w;
        int lmm = l * l + mi, lmn = l * l + ni;
        float zr = 0.f, zi = 0.f;
        #pragma unroll
        for (int i = 0; i < 16; i++) {
            float2 xv = Xs[i * NSPEC + lmm];
            float2 yv = Ys[i * NSPEC + lmn];
            zr += xv.x * yv.x - xv.y * yv.y;
            zi += xv.x * yv.y + xv.y * yv.x;
        }
        g_Z[(size_t)zo * NSO3 + j] = make_float2(zr, zi);
    }
}

// ---------------- synthesis: W accumulate + 2x separable 40-pt DFT ----------------
// grid (512, 5), block 512; each block: one (z,o), 8 output betas
__global__ void k_syn(const float* __restrict__ bias, float* __restrict__ out) {
    extern __shared__ float smraw[];
    float2* Zs  = (float2*)smraw;        // 10660
    float2* Ws  = Zs + NSO3;             // 39*39 = 1521
    float2* Ts  = Ws + 1521;             // 39*40 = 1560
    float2* tws = Ts + 1560;             // 40*39 = 1560  e^{2pi i (mi-19) a / 40}
    int zo = blockIdx.x;
    int tid = threadIdx.x;
    int nth = blockDim.x;

    for (int t = tid; t < NSO3; t += nth) Zs[t] = g_Z[(size_t)zo * NSO3 + t];
    for (int t = tid; t < 1560; t += nth) {
        int a = t / 39, mi = t % 39;
        float s, c;
        sincospif((float)((mi - 19) * a) / 20.0f, &s, &c);
        tws[t] = make_float2(c, s);
    }
    __syncthreads();

    float bias_o = bias[zo % 32];
    float* outbase = out + (size_t)zo * 64000;

    for (int bg = 0; bg < 8; bg++) {
        int b = blockIdx.y * 8 + bg;
        const float* db = g_dinv + (size_t)b * NSO3;

        // stage 1: W[mi][ni] = sum_l Z[l,m,n] * dinv[b][l,m,n]
        for (int q = tid; q < 1521; q += nth) {
            int miq = q / 39, niq = q % 39;
            int m = miq - 19, n = niq - 19;
            int am = m < 0 ? -m : m;
            int an = n < 0 ? -n : n;
            int lmin = am > an ? am : an;
            float wr = 0.f, wi = 0.f;
            for (int l = lmin; l < 20; l++) {
                int j = off3(l) + (m + l) * (2 * l + 1) + (n + l);
                float d = db[j];
                float2 zv = Zs[j];
                wr += zv.x * d;
                wi += zv.y * d;
            }
            Ws[q] = make_float2(wr, wi);
        }
        __syncthreads();

        // stage 2: T[mi][g] = sum_ni W[mi][ni] * e^{2pi i (ni-19) g / 40}
        for (int q = tid; q < 39 * 40; q += nth) {
            int miq = q / 40, g = q % 40;
            float tr = 0.f, ti = 0.f;
            const float2* wrow = Ws + miq * 39;
            const float2* trow = tws + g * 39;
            #pragma unroll 13
            for (int ni = 0; ni < 39; ni++) {
                float2 wv = wrow[ni];
                float2 ev = trow[ni];
                tr += wv.x * ev.x - wv.y * ev.y;
                ti += wv.x * ev.y + wv.y * ev.x;
            }
            Ts[miq * 40 + g] = make_float2(tr, ti);
        }
        __syncthreads();

        // stage 3: f[a][g] = Re sum_mi T[mi][g] * e^{2pi i (mi-19) a / 40}
        for (int q = tid; q < 1600; q += nth) {
            int a = q / 40, g = q % 40;
            float acc = 0.f;
            const float2* trow = tws + a * 39;
            #pragma unroll 13
            for (int mi = 0; mi < 39; mi++) {
                float2 tv = Ts[mi * 40 + g];
                float2 ev = trow[mi];
                acc += tv.x * ev.x - tv.y * ev.y;
            }
            outbase[(size_t)b * 1600 + q] = acc + bias_o;
        }
        __syncthreads();
    }
}

// ---------------- launch ----------------
extern "C" void kernel_launch(void* const* d_in, const int* in_sizes, int n_in,
                              void* d_out, int out_size) {
    const float* x    = (const float*)d_in[0];
    const float* ker  = (const float*)d_in[1];
    const float* bias = (const float*)d_in[2];
    float* out = (float*)d_out;

    const int SM_XFX = 128 * 128 * 4 + 2 * (128 * 39) * 8;          // 145408
    const int SM_Z   = 2 * 6400 * 8;                                // 102400
    const int SM_SYN = (NSO3 + 1521 + 1560 + 1560) * 8;             // 122408

    cudaFuncSetAttribute(k_xfX, cudaFuncAttributeMaxDynamicSharedMemorySize, SM_XFX);
    cudaFuncSetAttribute(k_Z,   cudaFuncAttributeMaxDynamicSharedMemorySize, SM_Z);
    cudaFuncSetAttribute(k_syn, cudaFuncAttributeMaxDynamicSharedMemorySize, SM_SYN);

    k_setup<<<1, 128>>>();
    k_ws2<<<(128 * NSPEC + 255) / 256, 256>>>();
    k_fk<<<(24 * NSPEC + 255) / 256, 256>>>();
    k_dinv<<<(40 * NSO3 + 255) / 256, 256>>>();
    k_Y<<<(32 * NSPEC * 16 + 255) / 256, 256>>>(ker);
    k_xfX<<<256, 256, SM_XFX>>>(x);
    k_Z<<<512, 256, SM_Z>>>();
    k_syn<<<dim3(NZO, 5), 512, SM_SYN>>>(bias, out);
}

// round 4
// speedup vs baseline: 2.1630x; 2.1630x over previous
#include <cuda_runtime.h>
#include <math.h>

// ---------------- problem constants ----------------
#define NSPEC 400
#define NSO3  10660
#define NZO   512          // 16*32
#define SCALING 0.008164965809277261f   // 1/sqrt(15000)

// ---------------- device scratch (allocation-free) ----------------
__device__ double g_quadw[128];
__device__ float  g_ws2[128 * NSPEC];          // [beta_in][lm]
__device__ float2 g_Fk[24 * NSPEC];            // [p][lm]
__device__ float2 g_Yc[32 * NSPEC * 16];       // [o][lm][i]  (= conj(Y)*SCALING)
__device__ float  g_dinv[40 * NSO3];           // [b][j], includes (2l+1)
__device__ float2 g_X[16 * NSPEC * 16];        // [z][lm][i]
__device__ float2 g_Z[NZO * NSO3];             // [zo][j]
__device__ uchar4 g_jmap[NSO3];                // j -> (l, mi, ni)

// ---------------- helpers ----------------
__device__ __forceinline__ int off3(int l) { return l * (4 * l * l - 1) / 3; }

__device__ __forceinline__ int l_of_lm(int lm) {
    int l = (int)sqrtf((float)lm);
    while ((l + 1) * (l + 1) <= lm) l++;
    while (l * l > lm) l--;
    return l;
}

__device__ __forceinline__ int l_of_j(int j) {
    int l = (int)cbrtf(0.75f * (float)j + 0.3f);
    if (l > 19) l = 19;
    while (l < 19 && off3(l + 1) <= j) l++;
    while (l > 0 && off3(l) > j) l--;
    return l;
}

// Seed d^{l0}_{m,n} at l0 = max(|m|,|n|), closed form.
__device__ double wig_seed(int l0, int m, int n, double cb, double sb) {
    int am = m < 0 ? -m : m, an = n < 0 ? -n : n;
    int k, pcb, psb, neg;
    if (an >= am) {
        k = m;
        if (n >= 0) { pcb = l0 + m; psb = l0 - m; neg = 0; }
        else        { pcb = l0 - m; psb = l0 + m; neg = (l0 + m) & 1; }
    } else {
        k = n;
        if (m >= 0) { pcb = l0 + n; psb = l0 - n; neg = (l0 + n) & 1; }
        else        { pcb = l0 - n; psb = l0 + n; neg = 0; }
    }
    int K = l0 + k;
    double C = 1.0;
    for (int i = 1; i <= K; i++) C *= (double)(2 * l0 - K + i) / (double)i;
    double v = sqrt(C);
    for (int i = 0; i < pcb; i++) v *= cb;
    for (int i = 0; i < psb; i++) v *= sb;
    return neg ? -v : v;
}

// Three-term recurrence in l (stable forward direction).
__device__ __forceinline__ double wig_next(int l, int m, int n, double x,
                                           double dl, double dlm1) {
    if (l == 1) return x * dl;   // only reachable for m=n=0
    double A = (double)(2 * l - 1) * ((double)(l * (l - 1)) * x - (double)(m * n));
    double lm1 = (double)(l - 1);
    double B = (double)l * sqrt((lm1 * lm1 - (double)(m * m)) * (lm1 * lm1 - (double)(n * n)));
    double Cd = (double)(l - 1) * sqrt(((double)(l * l) - (double)(m * m)) *
                                       ((double)(l * l) - (double)(n * n)));
    return (A * dl - B * dlm1) / Cd;
}

// ---------------- const generation ----------------
__global__ void k_setup() {
    int t = threadIdx.x;
    if (t < 128) {
        double th = M_PI * (2 * t + 1) / 256.0;
        double s = 0.0;
        for (int k = 0; k < 64; k++) s += sin((2 * k + 1) * th) / (2 * k + 1);
        g_quadw[t] = (2.0 / 64.0) * sin(th) * s;
    }
    for (int j = t; j < NSO3; j += blockDim.x) {
        int l = l_of_j(j);
        int rem = j - off3(l);
        int w = 2 * l + 1;
        g_jmap[j] = make_uchar4((unsigned char)l, (unsigned char)(rem / w),
                                (unsigned char)(rem % w), 0);
    }
}

// g_dinv via recurrence: thread per (b, mi, ni)
__global__ void k_dinv() {
    int id = blockIdx.x * blockDim.x + threadIdx.x;
    if (id >= 40 * 1521) return;
    int q = id % 1521, b = id / 1521;
    int m = q / 39 - 19, n = q % 39 - 19;
    double beta = M_PI * (2 * b + 1) / 80.0;
    double x = cos(beta), cb = cos(0.5 * beta), sb = sin(0.5 * beta);
    int am = m < 0 ? -m : m, an = n < 0 ? -n : n;
    int l0 = am > an ? am : an;
    double dl = wig_seed(l0, m, n, cb, sb), dlm1 = 0.0;
    {
        int l = l0;
        int j = off3(l) + (m + l) * (2 * l + 1) + (n + l);
        g_dinv[b * NSO3 + j] = (float)((2 * l + 1) * dl);
    }
    for (int l = l0 + 1; l <= 19; l++) {
        double nd = wig_next(l, m, n, x, dl, dlm1);
        dlm1 = dl; dl = nd;
        int j = off3(l) + (m + l) * (2 * l + 1) + (n + l);
        g_dinv[b * NSO3 + j] = (float)((2 * l + 1) * dl);
    }
}

// g_ws2 via recurrence: thread per (b, mi); n = 0
__global__ void k_ws2() {
    int id = blockIdx.x * blockDim.x + threadIdx.x;
    if (id >= 128 * 39) return;
    int mi = id % 39, b = id / 39;
    int m = mi - 19;
    double beta = M_PI * (2 * b + 1) / 256.0;
    double x = cos(beta), cb = cos(0.5 * beta), sb = sin(0.5 * beta);
    double qw = g_quadw[b];
    int l0 = m < 0 ? -m : m;
    double dl = wig_seed(l0, m, 0, cb, sb), dlm1 = 0.0;
    g_ws2[b * NSPEC + l0 * l0 + l0 + m] = (float)(qw * dl);
    for (int l = l0 + 1; l <= 19; l++) {
        double nd = wig_next(l, m, 0, x, dl, dlm1);
        dlm1 = dl; dl = nd;
        g_ws2[b * NSPEC + l * l + l + m] = (float)(qw * dl);
    }
}

// g_Fk via recurrence: thread per (p, mi); n = 0, phase e^{-i m alpha}
__global__ void k_fk() {
    int id = blockIdx.x * blockDim.x + threadIdx.x;
    if (id >= 24 * 39) return;
    int mi = id % 39, p = id / 39;
    int m = mi - 19;
    double beta = (M_PI / 24.0) * (double)(p / 8 + 1);
    int ai = p % 8;
    double x = cos(beta), cb = cos(0.5 * beta), sb = sin(0.5 * beta);
    double sa, ca;
    sincospi(-(double)(m * ai) / 4.0, &sa, &ca);
    int l0 = m < 0 ? -m : m;
    double dl = wig_seed(l0, m, 0, cb, sb), dlm1 = 0.0;
    g_Fk[p * NSPEC + l0 * l0 + l0 + m] = make_float2((float)(dl * ca), (float)(dl * sa));
    for (int l = l0 + 1; l <= 19; l++) {
        double nd = wig_next(l, m, 0, x, dl, dlm1);
        dlm1 = dl; dl = nd;
        g_Fk[p * NSPEC + l * l + l + m] = make_float2((float)(dl * ca), (float)(dl * sa));
    }
}

// Yc[o][lm][i] = SCALING * sum_p kernel[i][o][p] * conj(F_k[p][lm])
__global__ void k_Y(const float* __restrict__ ker) {
    int id = blockIdx.x * blockDim.x + threadIdx.x;
    if (id >= 32 * NSPEC * 16) return;
    int i = id % 16;
    int lm = (id / 16) % NSPEC;
    int o = id / (16 * NSPEC);
    float ar = 0.f, ai = 0.f;
    for (int p = 0; p < 24; p++) {
        float kv = ker[(i * 32 + o) * 24 + p];
        float2 f = g_Fk[p * NSPEC + lm];
        ar += kv * f.x;
        ai += kv * f.y;
    }
    g_Yc[id] = make_float2(SCALING * ar, -SCALING * ai);
}

// ---------------- alpha-DFT (m>=0 only, x real) + beta quadrature ----------------
__global__ void __launch_bounds__(256) k_xfX(const float* __restrict__ x) {
    extern __shared__ float sm[];
    float*  xs  = sm;                               // 128*128 floats
    float2* dft = (float2*)(sm + 128 * 128);        // [a][m], m = 0..19
    float2* xfs = dft + 128 * 20;                   // [b][m], m = 0..19
    int zi = blockIdx.x;
    int tid = threadIdx.x;
    const float* xp = x + (size_t)zi * 16384;
    for (int t = tid; t < 16384; t += blockDim.x) xs[t] = xp[t];
    for (int t = tid; t < 128 * 20; t += blockDim.x) {
        int a = t / 20, m = t % 20;
        float s, c;
        sincospif(-(float)(m * a) / 64.0f, &s, &c);     // e^{-2pi i m a / 128}
        dft[a * 20 + m] = make_float2(c, s);
    }
    __syncthreads();
    for (int t = tid; t < 128 * 20; t += blockDim.x) {
        int b = t / 20, m = t % 20;
        float ar = 0.f, ai = 0.f;
        const float* row = xs + b * 128;
        #pragma unroll 4
        for (int a = 0; a < 128; a++) {
            float2 w = dft[a * 20 + m];
            float v = row[a];
            ar += v * w.x;
            ai += v * w.y;
        }
        xfs[b * 20 + m] = make_float2(ar, ai);
    }
    __syncthreads();
    int z = zi / 16, i = zi % 16;
    for (int lm = tid; lm < NSPEC; lm += blockDim.x) {
        int l = l_of_lm(lm);
        int m = lm - l * l - l;
        int ma = m < 0 ? -m : m;
        float sgn = m < 0 ? -1.f : 1.f;   // xf[b,-m] = conj(xf[b,m])
        float ar = 0.f, ai = 0.f;
        for (int b = 0; b < 128; b++) {
            float w = g_ws2[b * NSPEC + lm];
            float2 v = xfs[b * 20 + ma];
            ar += w * v.x;
            ai += w * v.y;
        }
        g_X[(z * NSPEC + lm) * 16 + i] = make_float2(ar, sgn * ai);
    }
}

// ---------------- Z[zo][j] = sum_i X[z,i,lm_m] * Yc[o,lm_n,i] ----------------
__global__ void __launch_bounds__(256) k_Z() {
    extern __shared__ float2 sm2[];
    float2* Xs = sm2;          // [i][400]
    float2* Ys = sm2 + 6400;   // [i][400]
    int zo = blockIdx.x;
    int z = zo / 32, o = zo % 32;
    int tid = threadIdx.x;
    for (int t = tid; t < 6400; t += blockDim.x) {
        int lm = t / 16, i = t % 16;
        Xs[i * NSPEC + lm] = g_X[z * 6400 + t];
        Ys[i * NSPEC + lm] = g_Yc[o * 6400 + t];
    }
    __syncthreads();
    for (int j = tid; j < NSO3; j += blockDim.x) {
        uchar4 mp = g_jmap[j];
        int l = mp.x;
        int lmm = l * l + mp.y, lmn = l * l + mp.z;
        float zr = 0.f, zi = 0.f;
        #pragma unroll
        for (int i = 0; i < 16; i++) {
            float2 xv = Xs[i * NSPEC + lmm];
            float2 yv = Ys[i * NSPEC + lmn];
            zr += xv.x * yv.x - xv.y * yv.y;
            zi += xv.x * yv.y + xv.y * yv.x;
        }
        g_Z[(size_t)zo * NSO3 + j] = make_float2(zr, zi);
    }
}

// ---------------- synthesis with Hermitian symmetry + half-period twists ----------
// grid (512, 5), block 512; each block: one zo, 8 output betas.
// W[m>=0][n], T[m>=0][g] (g twist via (-1)^n), out via (-1)^m twist on a.
__global__ void __launch_bounds__(512) k_syn(const float* __restrict__ bias,
                                             float* __restrict__ out) {
    extern __shared__ float smraw[];
    float2* Zs = (float2*)smraw;         // 10660
    float2* Ws = Zs + NSO3;              // 20*39 = 780   [m][ni]
    float2* Ts = Ws + 780;               // 20*40 = 800   [m][g]
    float2* e2 = Ts + 800;               // 39*20 = 780   [ni][g]: e^{i n g th}
    float2* e3 = e2 + 780;               // 19*20 = 380   [m-1][a]: (2cos, 2sin)(m a th)
    int zo = blockIdx.x;
    int tid = threadIdx.x;
    int nth = blockDim.x;

    for (int t = tid; t < NSO3; t += nth) Zs[t] = g_Z[(size_t)zo * NSO3 + t];
    for (int t = tid; t < 780; t += nth) {
        int ni = t / 20, g = t % 20;
        int n = ni - 19;
        float s, c;
        sincospif((float)(n * g) / 20.0f, &s, &c);
        e2[ni * 20 + g] = make_float2(c, s);
    }
    for (int t = tid; t < 380; t += nth) {
        int m = t / 20 + 1, a = t % 20;
        float s, c;
        sincospif((float)(m * a) / 20.0f, &s, &c);
        e3[t] = make_float2(2.f * c, 2.f * s);
    }
    __syncthreads();

    float bias_o = bias[zo % 32];
    float* outbase = out + (size_t)zo * 64000;

    for (int bg = 0; bg < 8; bg++) {
        int b = blockIdx.y * 8 + bg;
        const float* db = g_dinv + (size_t)b * NSO3;

        // stage 1: W[m][ni] = sum_l Z[l,m,n]*dinv, m >= 0 only
        for (int q = tid; q < 780; q += nth) {
            int m = q / 39, n = q % 39 - 19;
            int an = n < 0 ? -n : n;
            int lmin = m > an ? m : an;
            float wr = 0.f, wi = 0.f;
            for (int l = lmin; l < 20; l++) {
                int j = off3(l) + (m + l) * (2 * l + 1) + (n + l);
                float d = db[j];
                float2 zv = Zs[j];
                wr += zv.x * d;
                wi += zv.y * d;
            }
            Ws[q] = make_float2(wr, wi);
        }
        __syncthreads();

        // stage 2: T[m][g] & T[m][g+20] via even/odd-ni accumulators
        for (int s = tid; s < 400; s += nth) {
            int m = s / 20, g = s % 20;
            const float2* wrow = Ws + m * 39;
            float aer = 0.f, aei = 0.f, aor = 0.f, aoi = 0.f;
            #pragma unroll
            for (int ni = 0; ni < 38; ni += 2) {
                float2 w0 = wrow[ni];
                float2 q0 = e2[ni * 20 + g];
                aer += w0.x * q0.x - w0.y * q0.y;
                aei += w0.x * q0.y + w0.y * q0.x;
                float2 w1 = wrow[ni + 1];
                float2 q1 = e2[(ni + 1) * 20 + g];
                aor += w1.x * q1.x - w1.y * q1.y;
                aoi += w1.x * q1.y + w1.y * q1.x;
            }
            {
                float2 w0 = wrow[38];
                float2 q0 = e2[38 * 20 + g];
                aer += w0.x * q0.x - w0.y * q0.y;
                aei += w0.x * q0.y + w0.y * q0.x;
            }
            // n = ni-19: ni even -> n odd (sign -), ni odd -> n even (sign +)
            Ts[m * 40 + g]      = make_float2(aer + aor, aei + aoi);
            Ts[m * 40 + g + 20] = make_float2(aor - aer, aoi - aei);
        }
        __syncthreads();

        // stage 3: out[a][g0,g1] and out[a+20][g0,g1], real cosine sum
        for (int s = tid; s < 400; s += nth) {
            int a = s / 20, gp = s % 20;
            int g0 = 2 * gp, g1 = 2 * gp + 1;
            float aE0 = Ts[g0].x, aE1 = Ts[g1].x;   // m = 0 (even)
            float aO0 = 0.f, aO1 = 0.f;
            #pragma unroll
            for (int m = 1; m < 19; m += 2) {
                float2 eo = e3[(m - 1) * 20 + a];
                float2 t0 = Ts[m * 40 + g0];
                float2 t1 = Ts[m * 40 + g1];
                aO0 += t0.x * eo.x - t0.y * eo.y;
                aO1 += t1.x * eo.x - t1.y * eo.y;
                float2 ee = e3[m * 20 + a];
                float2 u0 = Ts[(m + 1) * 40 + g0];
                float2 u1 = Ts[(m + 1) * 40 + g1];
                aE0 += u0.x * ee.x - u0.y * ee.y;
                aE1 += u1.x * ee.x - u1.y * ee.y;
            }
            {   // m = 19 (odd)
                float2 eo = e3[18 * 20 + a];
                float2 t0 = Ts[19 * 40 + g0];
                float2 t1 = Ts[19 * 40 + g1];
                aO0 += t0.x * eo.x - t0.y * eo.y;
                aO1 += t1.x * eo.x - t1.y * eo.y;
            }
            float* r0 = outbase + (size_t)b * 1600 + a * 40;
            float* r1 = r0 + 20 * 40;
            r0[g0] = aE0 + aO0 + bias_o;
            r0[g1] = aE1 + aO1 + bias_o;
            r1[g0] = aE0 - aO0 + bias_o;
            r1[g1] = aE1 - aO1 + bias_o;
        }
        __syncthreads();
    }
}

// ---------------- launch ----------------
extern "C" void kernel_launch(void* const* d_in, const int* in_sizes, int n_in,
                              void* d_out, int out_size) {
    const float* x    = (const float*)d_in[0];
    const float* ker  = (const float*)d_in[1];
    const float* bias = (const float*)d_in[2];
    float* out = (float*)d_out;

    const int SM_XFX = 128 * 128 * 4 + 2 * (128 * 20) * 8;              // 106496
    const int SM_Z   = 2 * 6400 * 8;                                    // 102400
    const int SM_SYN = (NSO3 + 780 + 800 + 780 + 380) * 8;              // 106560

    cudaFuncSetAttribute(k_xfX, cudaFuncAttributeMaxDynamicSharedMemorySize, SM_XFX);
    cudaFuncSetAttribute(k_Z,   cudaFuncAttributeMaxDynamicSharedMemorySize, SM_Z);
    cudaFuncSetAttribute(k_syn, cudaFuncAttributeMaxDynamicSharedMemorySize, SM_SYN);

    k_setup<<<1, 256>>>();
    k_ws2<<<(128 * 39 + 255) / 256, 256>>>();
    k_fk<<<(24 * 39 + 255) / 256, 256>>>();
    k_dinv<<<(40 * 1521 + 255) / 256, 256>>>();
    k_Y<<<(32 * NSPEC * 16 + 255) / 256, 256>>>(ker);
    k_xfX<<<256, 256, SM_XFX>>>(x);
    k_Z<<<512, 256, SM_Z>>>();
    k_syn<<<dim3(NZO, 5), 512, SM_SYN>>>(bias, out);
}

// round 6
// speedup vs baseline: 3.8547x; 1.7821x over previous
#include <cuda_runtime.h>
#include <math.h>

// ---------------- problem constants ----------------
#define NSPEC 400
#define NC    5530         // compact SO3 size: entries with m >= 0
#define NZO   512          // 16*32
#define SCALING 0.008164965809277261f   // 1/sqrt(15000)

// ---------------- device scratch (allocation-free) ----------------
__device__ float  g_quadw[128];
__device__ float  g_ws2[128 * NSPEC];          // [beta_in][lm]
__device__ float2 g_Fk[24 * NSPEC];            // [p][lm]
__device__ float2 g_Yc[32 * NSPEC * 16];       // [o][lm][i]  (= conj(Y)*SCALING)
__device__ float  g_dinv[40 * NC];             // [b][c] compact m>=0, includes (2l+1)
__device__ float2 g_X[16 * NSPEC * 16];        // [z][lm][i]
__device__ float2 g_Zc[(size_t)NZO * NC];      // [zo][c] compact m>=0
__device__ uchar4 g_jmapc[NC];                 // c -> (l, mi, ni)

// ---------------- helpers ----------------
// compact offset of level L: sum_{l<L} (l+1)(2l+1)
__device__ __forceinline__ int offc(int L) {
    return L == 0 ? 0 : ((L - 1) * L * (2 * L - 1)) / 3 + (3 * L * (L - 1)) / 2 + L;
}

__device__ __forceinline__ int l_of_lm(int lm) {
    int l = (int)sqrtf((float)lm);
    while ((l + 1) * (l + 1) <= lm) l++;
    while (l * l > lm) l--;
    return l;
}

// Seed d^{l0}_{m,n} at l0 = max(|m|,|n|), closed form, fp32.
__device__ float wig_seed(int l0, int m, int n, float cb, float sb) {
    int am = m < 0 ? -m : m, an = n < 0 ? -n : n;
    int k, pcb, psb, neg;
    if (an >= am) {
        k = m;
        if (n >= 0) { pcb = l0 + m; psb = l0 - m; neg = 0; }
        else        { pcb = l0 - m; psb = l0 + m; neg = (l0 + m) & 1; }
    } else {
        k = n;
        if (m >= 0) { pcb = l0 + n; psb = l0 - n; neg = (l0 + n) & 1; }
        else        { pcb = l0 - n; psb = l0 + n; neg = 0; }
    }
    int K = l0 + k;
    float C = 1.f;
    for (int i = 1; i <= K; i++) C *= (float)(2 * l0 - K + i) / (float)i;
    float v = sqrtf(C);
    for (int i = 0; i < pcb; i++) v *= cb;
    for (int i = 0; i < psb; i++) v *= sb;
    return neg ? -v : v;
}

// ---------------- const generation ----------------
__global__ void k_setup() {
    int t = threadIdx.x;
    if (t < 128) {
        float frac = (float)(2 * t + 1) / 256.f;
        float s = 0.f;
        for (int k = 0; k < 64; k++) s += sinpif((2 * k + 1) * frac) / (float)(2 * k + 1);
        g_quadw[t] = (2.f / 64.f) * sinpif(frac) * s;
    }
    for (int c = t; c < NC; c += blockDim.x) {
        int l = 0;
        while (l < 19 && offc(l + 1) <= c) l++;
        int rem = c - offc(l);
        int w = 2 * l + 1;
        int mloc = rem / w;        // m = mloc >= 0
        int ni = rem % w;
        g_jmapc[c] = make_uchar4((unsigned char)l, (unsigned char)(mloc + l),
                                 (unsigned char)ni, 0);
    }
}

// g_dinv (compact, m>=0) via fp32 recurrence: thread per (b, m, ni)
__global__ void k_dinv() {
    int id = blockIdx.x * blockDim.x + threadIdx.x;
    if (id >= 40 * 780) return;
    int q = id % 780, b = id / 780;
    int m = q / 39, n = q % 39 - 19;
    float beta = (float)M_PI * (float)(2 * b + 1) / 80.f;
    float x = cosf(beta), cb = cosf(0.5f * beta), sb = sinf(0.5f * beta);
    int an = n < 0 ? -n : n;
    int l0 = m > an ? m : an;
    float dl = wig_seed(l0, m, n, cb, sb), dlm1 = 0.f;
    float* db = g_dinv + b * NC;
    int cj = offc(l0) + m * (2 * l0 + 1) + (n + l0);
    db[cj] = (float)(2 * l0 + 1) * dl;
    float eprev = sqrtf((float)(l0 * l0 - m * m) * (float)(l0 * l0 - n * n));
    for (int l = l0 + 1; l <= 19; l++) {
        float nd;
        if (l == 1) { nd = x * dl; eprev = 1.f; }   // only m=n=0 reaches l0=0
        else {
            float el = sqrtf((float)(l * l - m * m) * (float)(l * l - n * n));
            float A = (float)(2 * l - 1) * ((float)(l * (l - 1)) * x - (float)(m * n));
            nd = __fdividef(A * dl - (float)l * eprev * dlm1, (float)(l - 1) * el);
            eprev = el;
        }
        dlm1 = dl; dl = nd;
        cj += l * (2 * l - 1) + 2 * m + 1;
        db[cj] = (float)(2 * l + 1) * dl;
    }
}

// g_ws2 via fp32 recurrence: thread per (b, mi); n = 0
__global__ void k_ws2() {
    int id = blockIdx.x * blockDim.x + threadIdx.x;
    if (id >= 128 * 39) return;
    int mi = id % 39, b = id / 39;
    int m = mi - 19;
    float beta = (float)M_PI * (float)(2 * b + 1) / 256.f;
    float x = cosf(beta), cb = cosf(0.5f * beta), sb = sinf(0.5f * beta);
    float qw = g_quadw[b];
    int l0 = m < 0 ? -m : m;
    float dl = wig_seed(l0, m, 0, cb, sb), dlm1 = 0.f;
    g_ws2[b * NSPEC + l0 * l0 + l0 + m] = qw * dl;
    float eprev = 0.f;   // sqrt((l0^2-m^2)*l0^2) = 0 since l0=|m|
    for (int l = l0 + 1; l <= 19; l++) {
        float nd;
        if (l == 1) { nd = x * dl; eprev = 1.f; }
        else {
            float el = sqrtf((float)(l * l - m * m)) * (float)l;
            float A = (float)(2 * l - 1) * (float)(l * (l - 1)) * x;
            nd = __fdividef(A * dl - (float)l * eprev * dlm1, (float)(l - 1) * el);
            eprev = el;
        }
        dlm1 = dl; dl = nd;
        g_ws2[b * NSPEC + l * l + l + m] = qw * dl;
    }
}

// g_Fk via fp32 recurrence: thread per (p, mi); n = 0, phase e^{-i m alpha}
__global__ void k_fk() {
    int id = blockIdx.x * blockDim.x + threadIdx.x;
    if (id >= 24 * 39) return;
    int mi = id % 39, p = id / 39;
    int m = mi - 19;
    float beta = ((float)M_PI / 24.f) * (float)(p / 8 + 1);
    int ai = p % 8;
    float x = cosf(beta), cb = cosf(0.5f * beta), sb = sinf(0.5f * beta);
    float sa, ca;
    sincospif(-(float)(m * ai) / 4.f, &sa, &ca);
    int l0 = m < 0 ? -m : m;
    float dl = wig_seed(l0, m, 0, cb, sb), dlm1 = 0.f;
    g_Fk[p * NSPEC + l0 * l0 + l0 + m] = make_float2(dl * ca, dl * sa);
    float eprev = 0.f;
    for (int l = l0 + 1; l <= 19; l++) {
        float nd;
        if (l == 1) { nd = x * dl; eprev = 1.f; }
        else {
            float el = sqrtf((float)(l * l - m * m)) * (float)l;
            float A = (float)(2 * l - 1) * (float)(l * (l - 1)) * x;
            nd = __fdividef(A * dl - (float)l * eprev * dlm1, (float)(l - 1) * el);
            eprev = el;
        }
        dlm1 = dl; dl = nd;
        g_Fk[p * NSPEC + l * l + l + m] = make_float2(dl * ca, dl * sa);
    }
}

// Yc[o][lm][i] = SCALING * sum_p kernel[i][o][p] * conj(F_k[p][lm])
__global__ void k_Y(const float* __restrict__ ker) {
    int id = blockIdx.x * blockDim.x + threadIdx.x;
    if (id >= 32 * NSPEC * 16) return;
    int i = id % 16;
    int lm = (id / 16) % NSPEC;
    int o = id / (16 * NSPEC);
    float ar = 0.f, ai = 0.f;
    for (int p = 0; p < 24; p++) {
        float kv = ker[(i * 32 + o) * 24 + p];
        float2 f = g_Fk[p * NSPEC + lm];
        ar += kv * f.x;
        ai += kv * f.y;
    }
    g_Yc[id] = make_float2(SCALING * ar, -SCALING * ai);
}

// ---------------- alpha-DFT (m>=0 only, x real) + beta quadrature ----------------
__global__ void __launch_bounds__(512) k_xfX(const float* __restrict__ x) {
    extern __shared__ float sm[];
    float*  xs  = sm;                               // 128*128 floats
    float2* dft = (float2*)(sm + 128 * 128);        // [a][m], m = 0..19
    float2* xfs = dft + 128 * 20;                   // [b][m], m = 0..19
    int zi = blockIdx.x;
    int tid = threadIdx.x;
    const float* xp = x + (size_t)zi * 16384;
    for (int t = tid; t < 16384; t += blockDim.x) xs[t] = xp[t];
    for (int t = tid; t < 128 * 20; t += blockDim.x) {
        int a = t / 20, m = t % 20;
        float s, c;
        sincospif(-(float)(m * a) / 64.0f, &s, &c);     // e^{-2pi i m a / 128}
        dft[a * 20 + m] = make_float2(c, s);
    }
    __syncthreads();
    for (int t = tid; t < 128 * 20; t += blockDim.x) {
        int b = t / 20, m = t % 20;
        float ar = 0.f, ai = 0.f;
        const float* row = xs + b * 128;
        #pragma unroll 4
        for (int a = 0; a < 128; a++) {
            float2 w = dft[a * 20 + m];
            float v = row[a];
            ar += v * w.x;
            ai += v * w.y;
        }
        xfs[b * 20 + m] = make_float2(ar, ai);
    }
    __syncthreads();
    int z = zi / 16, i = zi % 16;
    for (int lm = tid; lm < NSPEC; lm += blockDim.x) {
        int l = l_of_lm(lm);
        int m = lm - l * l - l;
        int ma = m < 0 ? -m : m;
        float sgn = m < 0 ? -1.f : 1.f;   // xf[b,-m] = conj(xf[b,m])
        float ar = 0.f, ai = 0.f;
        for (int b = 0; b < 128; b++) {
            float w = g_ws2[b * NSPEC + lm];
            float2 v = xfs[b * 20 + ma];
            ar += w * v.x;
            ai += w * v.y;
        }
        g_X[(z * NSPEC + lm) * 16 + i] = make_float2(ar, sgn * ai);
    }
}

// ---------------- Zc[zo][c] = sum_i X[z,i,lm_m] * Yc[o,lm_n,i], m>=0 only -------
__global__ void __launch_bounds__(512) k_Z() {
    extern __shared__ float2 sm2[];
    float2* Xs = sm2;          // [i][400]
    float2* Ys = sm2 + 6400;   // [i][400]
    int zo = blockIdx.x;
    int z = zo >> 5, o = zo & 31;
    int tid = threadIdx.x;
    for (int t = tid; t < 6400; t += blockDim.x) {
        int lm = t >> 4, i = t & 15;
        Xs[i * NSPEC + lm] = g_X[z * 6400 + t];
        Ys[i * NSPEC + lm] = g_Yc[o * 6400 + t];
    }
    __syncthreads();
    for (int c = tid; c < NC; c += blockDim.x) {
        uchar4 mp = g_jmapc[c];
        int l = mp.x;
        int lmm = l * l + mp.y, lmn = l * l + mp.z;
        float zr = 0.f, zi = 0.f;
        #pragma unroll
        for (int i = 0; i < 16; i++) {
            float2 xv = Xs[i * NSPEC + lmm];
            float2 yv = Ys[i * NSPEC + lmn];
            zr += xv.x * yv.x - xv.y * yv.y;
            zi += xv.x * yv.y + xv.y * yv.x;
        }
        g_Zc[(size_t)zo * NC + c] = make_float2(zr, zi);
    }
}

// ---------------- synthesis: Hermitian, compact Z, 2 betas per pass -------------
// grid (512, 5), block 512; each block: one zo, 8 output betas (4 passes x 2).
__global__ void __launch_bounds__(512, 2) k_syn(const float* __restrict__ bias,
                                                float* __restrict__ out) {
    extern __shared__ float smraw[];
    float2* Zs = (float2*)smraw;         // 5530 compact (m>=0)
    float2* Ws = Zs + NC;                // 2 x 780   [sub][m][ni]
    float2* Ts = Ws + 1560;              // 2 x 800   [sub][m][g]
    float2* e2 = Ts + 1600;              // 39*20     [ni][g]: e^{i n g th}
    float2* e3 = e2 + 780;               // 19*20     [m-1][a]: (2cos, 2sin)(m a th)
    int zo = blockIdx.x;
    int tid = threadIdx.x;
    const int nth = 512;

    for (int t = tid; t < NC; t += nth) Zs[t] = g_Zc[(size_t)zo * NC + t];
    for (int t = tid; t < 780; t += nth) {
        int ni = t / 20, g = t % 20;
        int n = ni - 19;
        float s, c;
        sincospif((float)(n * g) / 20.0f, &s, &c);
        e2[ni * 20 + g] = make_float2(c, s);
    }
    for (int t = tid; t < 380; t += nth) {
        int m = t / 20 + 1, a = t % 20;
        float s, c;
        sincospif((float)(m * a) / 20.0f, &s, &c);
        e3[t] = make_float2(2.f * c, 2.f * s);
    }
    __syncthreads();

    float bias_o = bias[zo & 31];
    float* outbase = out + (size_t)zo * 64000;

    for (int bg = 0; bg < 4; bg++) {
        int b0 = blockIdx.y * 8 + bg * 2;

        // stage 1: W[sub][m][ni] = sum_l Z[l,m,n]*dinv[b0+sub], m >= 0 only
        for (int q = tid; q < 1560; q += nth) {
            int sub = q >= 780 ? 1 : 0;
            int r = q - sub * 780;
            int m = r / 39, n = r % 39 - 19;
            const float* db = g_dinv + (b0 + sub) * NC;
            int an = n < 0 ? -n : n;
            int lmin = m > an ? m : an;
            int cj = offc(lmin) + m * (2 * lmin + 1) + (n + lmin);
            float wr = 0.f, wi = 0.f;
            for (int l = lmin; l < 20; l++) {
                float d = db[cj];
                float2 zv = Zs[cj];
                wr += zv.x * d;
                wi += zv.y * d;
                cj += (l + 1) * (2 * l + 1) + 2 * m + 1;
            }
            Ws[sub * 780 + r] = make_float2(wr, wi);
        }
        __syncthreads();

        // stage 2: T[m][g] & T[m][g+20] via even/odd-ni accumulators
        for (int s = tid; s < 800; s += nth) {
            int sub = s >= 400 ? 1 : 0;
            int r = s - sub * 400;
            int m = r / 20, g = r % 20;
            const float2* wrow = Ws + sub * 780 + m * 39;
            float aer = 0.f, aei = 0.f, aor = 0.f, aoi = 0.f;
            #pragma unroll
            for (int ni = 0; ni < 38; ni += 2) {
                float2 w0 = wrow[ni];
                float2 q0 = e2[ni * 20 + g];
                aer += w0.x * q0.x - w0.y * q0.y;
                aei += w0.x * q0.y + w0.y * q0.x;
                float2 w1 = wrow[ni + 1];
                float2 q1 = e2[(ni + 1) * 20 + g];
                aor += w1.x * q1.x - w1.y * q1.y;
                aoi += w1.x * q1.y + w1.y * q1.x;
            }
            {
                float2 w0 = wrow[38];
                float2 q0 = e2[38 * 20 + g];
                aer += w0.x * q0.x - w0.y * q0.y;
                aei += w0.x * q0.y + w0.y * q0.x;
            }
            // n = ni-19: ni even -> n odd (sign -), ni odd -> n even (sign +)
            float2* Tp = Ts + sub * 800;
            Tp[m * 40 + g]      = make_float2(aer + aor, aei + aoi);
            Tp[m * 40 + g + 20] = make_float2(aor - aer, aoi - aei);
        }
        __syncthreads();

        // stage 3: out[a][g0,g1] and out[a+20][g0,g1], real cosine sum
        for (int s = tid; s < 800; s += nth) {
            int sub = s >= 400 ? 1 : 0;
            int r = s - sub * 400;
            int a = r / 20, gp = r % 20;
            int g0 = 2 * gp, g1 = 2 * gp + 1;
            const float2* Tp = Ts + sub * 800;
            float aE0 = Tp[g0].x, aE1 = Tp[g1].x;   // m = 0 (even)
            float aO0 = 0.f, aO1 = 0.f;
            #pragma unroll
            for (int m = 1; m < 19; m += 2) {
                float2 eo = e3[(m - 1) * 20 + a];
                float2 t0 = Tp[m * 40 + g0];
                float2 t1 = Tp[m * 40 + g1];
                aO0 += t0.x * eo.x - t0.y * eo.y;
                aO1 += t1.x * eo.x - t1.y * eo.y;
                float2 ee = e3[m * 20 + a];
                float2 u0 = Tp[(m + 1) * 40 + g0];
                float2 u1 = Tp[(m + 1) * 40 + g1];
                aE0 += u0.x * ee.x - u0.y * ee.y;
                aE1 += u1.x * ee.x - u1.y * ee.y;
            }
            {   // m = 19 (odd)
                float2 eo = e3[18 * 20 + a];
                float2 t0 = Tp[19 * 40 + g0];
                float2 t1 = Tp[19 * 40 + g1];
                aO0 += t0.x * eo.x - t0.y * eo.y;
                aO1 += t1.x * eo.x - t1.y * eo.y;
            }
            float* r0 = outbase + (size_t)(b0 + sub) * 1600 + a * 40;
            float* r1 = r0 + 20 * 40;
            r0[g0] = aE0 + aO0 + bias_o;
            r0[g1] = aE1 + aO1 + bias_o;
            r1[g0] = aE0 - aO0 + bias_o;
            r1[g1] = aE1 - aO1 + bias_o;
        }
        __syncthreads();
    }
}

// ---------------- launch ----------------
extern "C" void kernel_launch(void* const* d_in, const int* in_sizes, int n_in,
                              void* d_out, int out_size) {
    const float* x    = (const float*)d_in[0];
    const float* ker  = (const float*)d_in[1];
    const float* bias = (const float*)d_in[2];
    float* out = (float*)d_out;

    const int SM_XFX = 128 * 128 * 4 + 2 * (128 * 20) * 8;              // 106496
    const int SM_Z   = 2 * 6400 * 8;                                    // 102400
    const int SM_SYN = (NC + 1560 + 1600 + 780 + 380) * 8;              // 78800

    cudaFuncSetAttribute(k_xfX, cudaFuncAttributeMaxDynamicSharedMemorySize, SM_XFX);
    cudaFuncSetAttribute(k_Z,   cudaFuncAttributeMaxDynamicSharedMemorySize, SM_Z);
    cudaFuncSetAttribute(k_syn, cudaFuncAttributeMaxDynamicSharedMemorySize, SM_SYN);

    k_setup<<<1, 256>>>();
    k_ws2<<<(128 * 39 + 255) / 256, 256>>>();
    k_fk<<<(24 * 39 + 255) / 256, 256>>>();
    k_dinv<<<(40 * 780 + 255) / 256, 256>>>();
    k_Y<<<(32 * NSPEC * 16 + 255) / 256, 256>>>(ker);
    k_xfX<<<256, 512, SM_XFX>>>(x);
    k_Z<<<512, 512, SM_Z>>>();
    k_syn<<<dim3(NZO, 5), 512, SM_SYN>>>(bias, out);
}

// round 15
// speedup vs baseline: 5.3906x; 1.3985x over previous
#include <cuda_runtime.h>
#include <math.h>

// ---------------- problem constants ----------------
#define NSPEC 400
#define NC    5530         // compact SO3 size: entries with m >= 0
#define NZO   512          // 16*32
#define SCALING 0.008164965809277261f   // 1/sqrt(15000)

// ---------------- device scratch (allocation-free) ----------------
__device__ float  g_quadw[128];
__device__ float  g_ws2[128 * NSPEC];          // [beta_in][lm]
__device__ float2 g_Fk[24 * NSPEC];            // [p][lm]
__device__ float2 g_Yc[32 * NSPEC * 16];       // [o][lm][i]  (= conj(Y)*SCALING)
__device__ float  g_dinv[40 * NC];             // [b][c] compact m>=0, includes (2l+1)
__device__ float2 g_X[16 * NSPEC * 16];        // [z][lm][i]
__device__ float2 g_Zc[(size_t)NZO * NC];      // [zo][c] compact m>=0
__device__ uchar4 g_jmapc[NC];                 // c -> (l, mi, ni)

// ---------------- helpers ----------------
// compact offset of level L: sum_{l<L} (l+1)(2l+1)
__device__ __forceinline__ int offc(int L) {
    return L == 0 ? 0 : ((L - 1) * L * (2 * L - 1)) / 3 + (3 * L * (L - 1)) / 2 + L;
}

__device__ __forceinline__ int l_of_lm(int lm) {
    int l = (int)sqrtf((float)lm);
    while ((l + 1) * (l + 1) <= lm) l++;
    while (l * l > lm) l--;
    return l;
}

// Seed d^{l0}_{m,n} at l0 = max(|m|,|n|), closed form, fp32.
__device__ float wig_seed(int l0, int m, int n, float cb, float sb) {
    int am = m < 0 ? -m : m, an = n < 0 ? -n : n;
    int k, pcb, psb, neg;
    if (an >= am) {
        k = m;
        if (n >= 0) { pcb = l0 + m; psb = l0 - m; neg = 0; }
        else        { pcb = l0 - m; psb = l0 + m; neg = (l0 + m) & 1; }
    } else {
        k = n;
        if (m >= 0) { pcb = l0 + n; psb = l0 - n; neg = (l0 + n) & 1; }
        else        { pcb = l0 - n; psb = l0 + n; neg = 0; }
    }
    int K = l0 + k;
    float C = 1.f;
    for (int i = 1; i <= K; i++) C *= (float)(2 * l0 - K + i) / (float)i;
    float v = sqrtf(C);
    for (int i = 0; i < pcb; i++) v *= cb;
    for (int i = 0; i < psb; i++) v *= sb;
    return neg ? -v : v;
}

// ---------------- const generation ----------------
__global__ void k_setup() {
    int t = threadIdx.x;
    if (t < 128) {
        float frac = (float)(2 * t + 1) / 256.f;
        float s = 0.f;
        for (int k = 0; k < 64; k++) s += sinpif((2 * k + 1) * frac) / (float)(2 * k + 1);
        g_quadw[t] = (2.f / 64.f) * sinpif(frac) * s;
    }
    for (int c = t; c < NC; c += blockDim.x) {
        int l = 0;
        while (l < 19 && offc(l + 1) <= c) l++;
        int rem = c - offc(l);
        int w = 2 * l + 1;
        int mloc = rem / w;        // m = mloc >= 0
        int ni = rem % w;
        g_jmapc[c] = make_uchar4((unsigned char)l, (unsigned char)(mloc + l),
                                 (unsigned char)ni, 0);
    }
}

// g_dinv (compact, m>=0) via fp32 recurrence: thread per (b, m, ni)
__global__ void k_dinv() {
    int id = blockIdx.x * blockDim.x + threadIdx.x;
    if (id >= 40 * 780) return;
    int q = id % 780, b = id / 780;
    int m = q / 39, n = q % 39 - 19;
    float beta = (float)M_PI * (float)(2 * b + 1) / 80.f;
    float x = cosf(beta), cb = cosf(0.5f * beta), sb = sinf(0.5f * beta);
    int an = n < 0 ? -n : n;
    int l0 = m > an ? m : an;
    float dl = wig_seed(l0, m, n, cb, sb), dlm1 = 0.f;
    float* db = g_dinv + b * NC;
    int cj = offc(l0) + m * (2 * l0 + 1) + (n + l0);
    db[cj] = (float)(2 * l0 + 1) * dl;
    float eprev = sqrtf((float)(l0 * l0 - m * m) * (float)(l0 * l0 - n * n));
    for (int l = l0 + 1; l <= 19; l++) {
        float nd;
        if (l == 1) { nd = x * dl; eprev = 1.f; }   // only m=n=0 reaches l0=0
        else {
            float el = sqrtf((float)(l * l - m * m) * (float)(l * l - n * n));
            float A = (float)(2 * l - 1) * ((float)(l * (l - 1)) * x - (float)(m * n));
            nd = __fdividef(A * dl - (float)l * eprev * dlm1, (float)(l - 1) * el);
            eprev = el;
        }
        dlm1 = dl; dl = nd;
        cj += l * (2 * l - 1) + 2 * m + 1;
        db[cj] = (float)(2 * l + 1) * dl;
    }
}

// g_ws2 via fp32 recurrence: thread per (b, mi); n = 0
__global__ void k_ws2() {
    int id = blockIdx.x * blockDim.x + threadIdx.x;
    if (id >= 128 * 39) return;
    int mi = id % 39, b = id / 39;
    int m = mi - 19;
    float beta = (float)M_PI * (float)(2 * b + 1) / 256.f;
    float x = cosf(beta), cb = cosf(0.5f * beta), sb = sinf(0.5f * beta);
    float qw = g_quadw[b];
    int l0 = m < 0 ? -m : m;
    float dl = wig_seed(l0, m, 0, cb, sb), dlm1 = 0.f;
    g_ws2[b * NSPEC + l0 * l0 + l0 + m] = qw * dl;
    float eprev = 0.f;   // sqrt((l0^2-m^2)*l0^2) = 0 since l0=|m|
    for (int l = l0 + 1; l <= 19; l++) {
        float nd;
        if (l == 1) { nd = x * dl; eprev = 1.f; }
        else {
            float el = sqrtf((float)(l * l - m * m)) * (float)l;
            float A = (float)(2 * l - 1) * (float)(l * (l - 1)) * x;
            nd = __fdividef(A * dl - (float)l * eprev * dlm1, (float)(l - 1) * el);
            eprev = el;
        }
        dlm1 = dl; dl = nd;
        g_ws2[b * NSPEC + l * l + l + m] = qw * dl;
    }
}

// g_Fk via fp32 recurrence: thread per (p, mi); n = 0, phase e^{-i m alpha}
__global__ void k_fk() {
    int id = blockIdx.x * blockDim.x + threadIdx.x;
    if (id >= 24 * 39) return;
    int mi = id % 39, p = id / 39;
    int m = mi - 19;
    float beta = ((float)M_PI / 24.f) * (float)(p / 8 + 1);
    int ai = p % 8;
    float x = cosf(beta), cb = cosf(0.5f * beta), sb = sinf(0.5f * beta);
    float sa, ca;
    sincospif(-(float)(m * ai) / 4.f, &sa, &ca);
    int l0 = m < 0 ? -m : m;
    float dl = wig_seed(l0, m, 0, cb, sb), dlm1 = 0.f;
    g_Fk[p * NSPEC + l0 * l0 + l0 + m] = make_float2(dl * ca, dl * sa);
    float eprev = 0.f;
    for (int l = l0 + 1; l <= 19; l++) {
        float nd;
        if (l == 1) { nd = x * dl; eprev = 1.f; }
        else {
            float el = sqrtf((float)(l * l - m * m)) * (float)l;
            float A = (float)(2 * l - 1) * (float)(l * (l - 1)) * x;
            nd = __fdividef(A * dl - (float)l * eprev * dlm1, (float)(l - 1) * el);
            eprev = el;
        }
        dlm1 = dl; dl = nd;
        g_Fk[p * NSPEC + l * l + l + m] = make_float2(dl * ca, dl * sa);
    }
}

// Yc[o][lm][i] = SCALING * sum_p kernel[i][o][p] * conj(F_k[p][lm])
// grid (32, 4): block = (o, 100-lm chunk); Fk chunk + kernel slice staged in smem
__global__ void __launch_bounds__(512) k_Y(const float* __restrict__ ker) {
    __shared__ float2 Fs[24 * 100];
    __shared__ float  ks[16 * 24];
    int o = blockIdx.x, lm0 = blockIdx.y * 100;
    int tid = threadIdx.x;
    for (int t = tid; t < 2400; t += 512) {
        int p = t / 100, lm = t % 100;
        Fs[t] = g_Fk[p * NSPEC + lm0 + lm];
    }
    for (int t = tid; t < 384; t += 512) {
        int i = t / 24, p = t % 24;
        ks[t] = ker[(i * 32 + o) * 24 + p] * SCALING;
    }
    __syncthreads();
    for (int c = tid; c < 1600; c += 512) {
        int lm = c >> 4, i = c & 15;
        float ar = 0.f, ai = 0.f;
        #pragma unroll
        for (int p = 0; p < 24; p++) {
            float kv = ks[i * 24 + p];
            float2 f = Fs[p * 100 + lm];
            ar += kv * f.x;
            ai += kv * f.y;
        }
        g_Yc[(size_t)o * 6400 + (lm0 + lm) * 16 + i] = make_float2(ar, -ai);
    }
}

// ---------------- alpha-DFT (m>=0 only, x real) + beta quadrature ----------------
// xs padded to 129 floats/row (bank-conflict-free 2b tiling); DFT stage tiled 2b x 2m
__global__ void __launch_bounds__(512) k_xfX(const float* __restrict__ x) {
    extern __shared__ float sm[];
    float*  xs  = sm;                               // 128 x 129 floats (padded)
    float2* dft = (float2*)(sm + 128 * 129);        // [a][m], m = 0..19
    float2* xfs = dft + 128 * 20;                   // [b][m], m = 0..19
    int zi = blockIdx.x;
    int tid = threadIdx.x;
    const float* xp = x + (size_t)zi * 16384;
    for (int t = tid; t < 16384; t += 512)
        xs[(t >> 7) * 129 + (t & 127)] = xp[t];
    for (int t = tid; t < 2560; t += 512) {
        int a = t / 20, m = t % 20;
        float s, c;
        sincospif(-(float)(m * a) / 64.0f, &s, &c);     // e^{-2pi i m a / 128}
        dft[t] = make_float2(c, s);
    }
    __syncthreads();
    // DFT tiles: 64 b-pairs x 10 m-pairs
    for (int t = tid; t < 640; t += 512) {
        int b0 = (t / 10) * 2, m0 = (t % 10) * 2;
        const float* r0 = xs + b0 * 129;
        const float* r1 = r0 + 129;
        float a00r = 0.f, a00i = 0.f, a01r = 0.f, a01i = 0.f;
        float a10r = 0.f, a10i = 0.f, a11r = 0.f, a11i = 0.f;
        #pragma unroll 8
        for (int a = 0; a < 128; a++) {
            float va = r0[a], vb = r1[a];
            float4 dd = *(const float4*)(dft + a * 20 + m0);
            a00r += va * dd.x; a00i += va * dd.y;
            a01r += va * dd.z; a01i += va * dd.w;
            a10r += vb * dd.x; a10i += vb * dd.y;
            a11r += vb * dd.z; a11i += vb * dd.w;
        }
        xfs[b0 * 20 + m0]           = make_float2(a00r, a00i);
        xfs[b0 * 20 + m0 + 1]       = make_float2(a01r, a01i);
        xfs[(b0 + 1) * 20 + m0]     = make_float2(a10r, a10i);
        xfs[(b0 + 1) * 20 + m0 + 1] = make_float2(a11r, a11i);
    }
    __syncthreads();
    int z = zi / 16, i = zi % 16;
    for (int lm = tid; lm < NSPEC; lm += 512) {
        int l = l_of_lm(lm);
        int m = lm - l * l - l;
        int ma = m < 0 ? -m : m;
        float sgn = m < 0 ? -1.f : 1.f;   // xf[b,-m] = conj(xf[b,m])
        float ar = 0.f, ai = 0.f;
        for (int b = 0; b < 128; b++) {
            float w = g_ws2[b * NSPEC + lm];
            float2 v = xfs[b * 20 + ma];
            ar += w * v.x;
            ai += w * v.y;
        }
        g_X[(z * NSPEC + lm) * 16 + i] = make_float2(ar, sgn * ai);
    }
}

// ---------------- Zc[zo][c] = sum_i X[z,i,lm_m] * Yc[o,lm_n,i], m>=0 only -------
__global__ void __launch_bounds__(512) k_Z() {
    extern __shared__ float2 sm2[];
    float2* Xs = sm2;          // [i][400]
    float2* Ys = sm2 + 6400;   // [i][400]
    int zo = blockIdx.x;
    int z = zo >> 5, o = zo & 31;
    int tid = threadIdx.x;
    for (int t = tid; t < 6400; t += blockDim.x) {
        int lm = t >> 4, i = t & 15;
        Xs[i * NSPEC + lm] = g_X[z * 6400 + t];
        Ys[i * NSPEC + lm] = g_Yc[o * 6400 + t];
    }
    __syncthreads();
    for (int c = tid; c < NC; c += blockDim.x) {
        uchar4 mp = g_jmapc[c];
        int l = mp.x;
        int lmm = l * l + mp.y, lmn = l * l + mp.z;
        float zr = 0.f, zi = 0.f;
        #pragma unroll
        for (int i = 0; i < 16; i++) {
            float2 xv = Xs[i * NSPEC + lmm];
            float2 yv = Ys[i * NSPEC + lmn];
            zr += xv.x * yv.x - xv.y * yv.y;
            zi += xv.x * yv.y + xv.y * yv.x;
        }
        g_Zc[(size_t)zo * NC + c] = make_float2(zr, zi);
    }
}

// ---------------- synthesis: Hermitian, compact Z, register-tiled stages --------
// grid (512, 5), block 512; each block: one zo, 8 output betas (4 passes x 2).
__global__ void __launch_bounds__(512, 2) k_syn(const float* __restrict__ bias,
                                                float* __restrict__ out) {
    extern __shared__ float smraw[];
    float2* Zs = (float2*)smraw;         // 5530 compact (m>=0)
    float2* Ws = Zs + NC;                // 2 x 780   [sub][m][ni]
    float2* Ts = Ws + 1560;              // 2 x 800   [sub][m][g]
    float2* e2 = Ts + 1600;              // 39*20     [k][g]: e^{i (k-19) g pi/20}
    int zo = blockIdx.x;
    int tid = threadIdx.x;
    const int nth = 512;

    for (int t = tid; t < NC; t += nth) Zs[t] = g_Zc[(size_t)zo * NC + t];
    for (int t = tid; t < 780; t += nth) {
        int k = t / 20, g = t % 20;
        float s, c;
        sincospif((float)((k - 19) * g) / 20.0f, &s, &c);
        e2[t] = make_float2(c, s);
    }
    __syncthreads();

    float bias_o = bias[zo & 31];
    float* outbase = out + (size_t)zo * 64000;

    for (int bg = 0; bg < 4; bg++) {
        int b0 = blockIdx.y * 8 + bg * 2;
        const float* d0 = g_dinv + b0 * NC;
        const float* d1 = d0 + NC;

        // stage 1: W[sub][m][ni] for both betas from one Z scan
        for (int q = tid; q < 780; q += nth) {
            int m = q / 39, n = q % 39 - 19;
            int an = n < 0 ? -n : n;
            int lmin = m > an ? m : an;
            int cj = offc(lmin) + m * (2 * lmin + 1) + (n + lmin);
            float w0r = 0.f, w0i = 0.f, w1r = 0.f, w1i = 0.f;
            for (int l = lmin; l < 20; l++) {
                float2 zv = Zs[cj];
                float da = d0[cj], db = d1[cj];
                w0r += zv.x * da; w0i += zv.y * da;
                w1r += zv.x * db; w1i += zv.y * db;
                cj += (l + 1) * (2 * l + 1) + 2 * m + 1;
            }
            Ws[q]       = make_float2(w0r, w0i);
            Ws[780 + q] = make_float2(w1r, w1i);
        }
        __syncthreads();

        // stage 2: 2m x 2g tiles over adjacent g (g0, g0+1); A = even-ni, B = odd-ni
        // T[g] = A + B; T[g+20] = B - A  (n = ni-19 parity; g covers 0..19 here,
        // +20 columns come from the parity twist)
        for (int t = tid; t < 200; t += nth) {
            int sub = t >= 100 ? 1 : 0;
            int r = t - sub * 100;
            int m0 = (r / 10) * 2, g0 = (r % 10) * 2;
            const float2* w0 = Ws + sub * 780 + m0 * 39;
            const float2* w1 = w0 + 39;
            float A00r=0,A00i=0,A01r=0,A01i=0,A10r=0,A10i=0,A11r=0,A11i=0;
            float B00r=0,B00i=0,B01r=0,B01i=0,B10r=0,B10i=0,B11r=0,B11i=0;
            #pragma unroll
            for (int ni = 0; ni < 38; ni += 2) {
                float2 wa = w0[ni], wb = w1[ni];
                float2 qa = e2[ni * 20 + g0], qb = e2[ni * 20 + g0 + 1];
                A00r += wa.x*qa.x - wa.y*qa.y; A00i += wa.x*qa.y + wa.y*qa.x;
                A01r += wa.x*qb.x - wa.y*qb.y; A01i += wa.x*qb.y + wa.y*qb.x;
                A10r += wb.x*qa.x - wb.y*qa.y; A10i += wb.x*qa.y + wb.y*qa.x;
                A11r += wb.x*qb.x - wb.y*qb.y; A11i += wb.x*qb.y + wb.y*qb.x;
                wa = w0[ni + 1]; wb = w1[ni + 1];
                qa = e2[(ni + 1) * 20 + g0]; qb = e2[(ni + 1) * 20 + g0 + 1];
                B00r += wa.x*qa.x - wa.y*qa.y; B00i += wa.x*qa.y + wa.y*qa.x;
                B01r += wa.x*qb.x - wa.y*qb.y; B01i += wa.x*qb.y + wa.y*qb.x;
                B10r += wb.x*qa.x - wb.y*qa.y; B10i += wb.x*qa.y + wb.y*qa.x;
                B11r += wb.x*qb.x - wb.y*qb.y; B11i += wb.x*qb.y + wb.y*qb.x;
            }
            {   // ni = 38 (even)
                float2 wa = w0[38], wb = w1[38];
                float2 qa = e2[38 * 20 + g0], qb = e2[38 * 20 + g0 + 1];
                A00r += wa.x*qa.x - wa.y*qa.y; A00i += wa.x*qa.y + wa.y*qa.x;
                A01r += wa.x*qb.x - wa.y*qb.y; A01i += wa.x*qb.y + wa.y*qb.x;
                A10r += wb.x*qa.x - wb.y*qa.y; A10i += wb.x*qa.y + wb.y*qa.x;
                A11r += wb.x*qb.x - wb.y*qb.y; A11i += wb.x*qb.y + wb.y*qb.x;
            }
            float2* Tp = Ts + sub * 800;
            Tp[m0*40 + g0]          = make_float2(A00r + B00r, A00i + B00i);
            Tp[m0*40 + g0 + 20]     = make_float2(B00r - A00r, B00i - A00i);
            Tp[m0*40 + g0 + 1]      = make_float2(A01r + B01r, A01i + B01i);
            Tp[m0*40 + g0 + 21]     = make_float2(B01r - A01r, B01i - A01i);
            Tp[(m0+1)*40 + g0]      = make_float2(A10r + B10r, A10i + B10i);
            Tp[(m0+1)*40 + g0 + 20] = make_float2(B10r - A10r, B10i - A10i);
            Tp[(m0+1)*40 + g0 + 1]  = make_float2(A11r + B11r, A11i + B11i);
            Tp[(m0+1)*40 + g0 + 21] = make_float2(B11r - A11r, B11i - A11i);
        }
        __syncthreads();

        // stage 3: 2a x 2g tiles; E = even-m, O = odd-m real partials.
        // The a-parity twist gives rows a+20; g must cover ALL 20 pairs
        // (g0 = 0..38 even), hence 200 tiles per sub (NOT 100 as in stage 2).
        // out[a][g] = T0 + 2(E+O); out[a+20][g] = T0 + 2(E-O)
        for (int t = tid; t < 400; t += nth) {
            int sub = t >= 200 ? 1 : 0;
            int r = t - sub * 200;
            int a0 = (r / 20) * 2, gp = r % 20;
            int g0 = 2 * gp;
            const float2* Tp = Ts + sub * 800;
            float E00=0,O00=0,E01=0,O01=0,E10=0,O10=0,E11=0,O11=0;
            #pragma unroll
            for (int m = 1; m < 19; m += 2) {
                float2 t0 = Tp[m*40 + g0], t1 = Tp[m*40 + g0 + 1];
                float2 ea = e2[(m+19)*20 + a0], eb = e2[(m+19)*20 + a0 + 1];
                O00 += t0.x*ea.x - t0.y*ea.y; O01 += t1.x*ea.x - t1.y*ea.y;
                O10 += t0.x*eb.x - t0.y*eb.y; O11 += t1.x*eb.x - t1.y*eb.y;
                t0 = Tp[(m+1)*40 + g0]; t1 = Tp[(m+1)*40 + g0 + 1];
                ea = e2[(m+20)*20 + a0]; eb = e2[(m+20)*20 + a0 + 1];
                E00 += t0.x*ea.x - t0.y*ea.y; E01 += t1.x*ea.x - t1.y*ea.y;
                E10 += t0.x*eb.x - t0.y*eb.y; E11 += t1.x*eb.x - t1.y*eb.y;
            }
            {   // m = 19 (odd)
                float2 t0 = Tp[19*40 + g0], t1 = Tp[19*40 + g0 + 1];
                float2 ea = e2[38*20 + a0], eb = e2[38*20 + a0 + 1];
                O00 += t0.x*ea.x - t0.y*ea.y; O01 += t1.x*ea.x - t1.y*ea.y;
                O10 += t0.x*eb.x - t0.y*eb.y; O11 += t1.x*eb.x - t1.y*eb.y;
            }
            float T0g0 = Tp[g0].x, T0g1 = Tp[g0 + 1].x;
            float* rb = outbase + (size_t)(b0 + sub) * 1600;
            rb[a0*40 + g0]          = T0g0 + 2.f*(E00 + O00) + bias_o;
            rb[a0*40 + g0 + 1]      = T0g1 + 2.f*(E01 + O01) + bias_o;
            rb[(a0+20)*40 + g0]     = T0g0 + 2.f*(E00 - O00) + bias_o;
            rb[(a0+20)*40 + g0 + 1] = T0g1 + 2.f*(E01 - O01) + bias_o;
            rb[(a0+1)*40 + g0]      = T0g0 + 2.f*(E10 + O10) + bias_o;
            rb[(a0+1)*40 + g0 + 1]  = T0g1 + 2.f*(E11 + O11) + bias_o;
            rb[(a0+21)*40 + g0]     = T0g0 + 2.f*(E10 - O10) + bias_o;
            rb[(a0+21)*40 + g0 + 1] = T0g1 + 2.f*(E11 - O11) + bias_o;
        }
        __syncthreads();
    }
}

// ---------------- launch ----------------
extern "C" void kernel_launch(void* const* d_in, const int* in_sizes, int n_in,
                              void* d_out, int out_size) {
    const float* x    = (const float*)d_in[0];
    const float* ker  = (const float*)d_in[1];
    const float* bias = (const float*)d_in[2];
    float* out = (float*)d_out;

    const int SM_XFX = 128 * 129 * 4 + 2 * (128 * 20) * 8;              // 107008
    const int SM_Z   = 2 * 6400 * 8;                                    // 102400
    const int SM_SYN = (NC + 1560 + 1600 + 780) * 8;                    // 75760

    cudaFuncSetAttribute(k_xfX, cudaFuncAttributeMaxDynamicSharedMemorySize, SM_XFX);
    cudaFuncSetAttribute(k_Z,   cudaFuncAttributeMaxDynamicSharedMemorySize, SM_Z);
    cudaFuncSetAttribute(k_syn, cudaFuncAttributeMaxDynamicSharedMemorySize, SM_SYN);

    k_setup<<<1, 256>>>();
    k_ws2<<<(128 * 39 + 255) / 256, 256>>>();
    k_fk<<<(24 * 39 + 255) / 256, 256>>>();
    k_dinv<<<(40 * 780 + 255) / 256, 256>>>();
    k_Y<<<dim3(32, 4), 512>>>(ker);
    k_xfX<<<256, 512, SM_XFX>>>(x);
    k_Z<<<512, 512, SM_Z>>>();
    k_syn<<<dim3(NZO, 5), 512, SM_SYN>>>(bias, out);
}